// round 16
// baseline (speedup 1.0000x reference)
#include <cuda_runtime.h>
#include <cuda_bf16.h>
#include <math.h>
#include <stdint.h>
#include <mma.h>

using namespace nvcuda;

#define MB   256
#define TX   256
#define FDIM 128
#define NA   256
#define NS   512
#define VOC  1024
#define AH   10
#define TYD  10

#define XBLD 72
#define XALD 136
#define XCLD 72

#define BLD  72    // decoder B smem ld
#define CLD  72    // decoder C smem ld
#define DALD 264   // decoder A smem ld

#define LALD 264   // lstm A smem ld (bf16), k=256
#define LWLD 1032  // lstm W-chunk smem ld (bf16), 1024 cols
#define LCLD 1032  // lstm C smem ld (float)
#define RK   32    // lstm K chunk

// ---------------- scratch ----------------
__device__ float    g_gin[2][TX][MB][4 * NA];   // [m][u*4+g]
__device__ unsigned g_abf[TX][MB][NS / 2];      // bf16x2 encoder states
__device__ __nv_bfloat16 g_whx[2][2][NA][1024]; // lstm W planes [dir][pl][k][c=u*4+g]
__device__ float    g_Ea[MB][TX][AH];
__device__ unsigned g_cx[2][MB][NS / 2];        // ctx bf16 planes
__device__ unsigned g_sx[2][2][MB][NS / 2];     // s planes [buf][pl][m][k2]
__device__ float    g_sbuf[2][MB][NS];
__device__ float    g_cdec[MB][NS];
__device__ __nv_bfloat16 g_wdx[2][1024][2048];  // dec W planes
__device__ __nv_bfloat16 g_wfx[2][512][1024];   // fc W planes

__device__ __forceinline__ float sigf(float x) { return 1.f / (1.f + expf(-x)); }
__device__ __forceinline__ float fsig(float x) { return __fdividef(1.f, 1.f + __expf(-x)); }
__device__ __forceinline__ float ftanh(float x) { return 1.f - __fdividef(2.f, __expf(2.f * x) + 1.f); }

__global__ void init_dec_kernel()
{
    int i = blockIdx.x * 256 + threadIdx.x;
    if (i < MB * NS) {
        (&g_sbuf[0][0][0])[i] = 0.f;
        (&g_cdec[0][0])[i] = 0.f;
        ((unsigned*)&g_sx[0][0][0][0])[i] = 0u;
    }
}

// ---------------- weight-split preps ----------------
__global__ void whx_prep(const float* __restrict__ Whf, const float* __restrict__ Whb)
{
    int idx = blockIdx.x * 256 + threadIdx.x;       // 2*256*1024
    int d = idx >> 18;
    int k = (idx >> 10) & 255;
    int c = idx & 1023;
    int u = c >> 2, g = c & 3;
    const float* W = d ? Whb : Whf;
    float w = W[(size_t)(g * NA + u) * NA + k];
    __nv_bfloat16 hi = __float2bfloat16(w);
    __nv_bfloat16 lo = __float2bfloat16(w - __bfloat162float(hi));
    g_whx[d][0][k][c] = hi;
    g_whx[d][1][k][c] = lo;
}

__global__ void wdx_prep(const float* __restrict__ Wc_ih, const float* __restrict__ Wc_hh)
{
    int idx = blockIdx.x * 256 + threadIdx.x;
    int k = idx >> 11, c = idx & 2047;
    int u = c >> 2, g = c & 3;
    float w = (k < NS) ? Wc_ih[(size_t)(g * NS + u) * NS + k]
                       : Wc_hh[(size_t)(g * NS + u) * NS + (k - NS)];
    __nv_bfloat16 hi = __float2bfloat16(w);
    __nv_bfloat16 lo = __float2bfloat16(w - __bfloat162float(hi));
    g_wdx[0][k][c] = hi;
    g_wdx[1][k][c] = lo;
}

__global__ void wfx_prep(const float* __restrict__ Wfc)
{
    int idx = blockIdx.x * 256 + threadIdx.x;
    int k = idx >> 10, c = idx & 1023;
    float w = Wfc[(size_t)c * NS + k];
    __nv_bfloat16 hi = __float2bfloat16(w);
    __nv_bfloat16 lo = __float2bfloat16(w - __bfloat162float(hi));
    g_wfx[0][k][c] = hi;
    g_wfx[1][k][c] = lo;
}

// ---------------- encoder input projection (R14-validated wmma) ----------------
__global__ void __launch_bounds__(128) xproj_kernel(const float* __restrict__ X,
                             const float* __restrict__ Wf, const float* __restrict__ bf,
                             const float* __restrict__ Wb, const float* __restrict__ bb)
{
    extern __shared__ char xsm[];
    __nv_bfloat16* Bhi = (__nv_bfloat16*)xsm;
    __nv_bfloat16* Blo = Bhi + 128 * XBLD;
    __nv_bfloat16* Ahi = Blo + 128 * XBLD;
    __nv_bfloat16* Alo = Ahi + 64 * XALD;
    float*         Cs  = (float*)(Alo + 64 * XALD);

    int d = blockIdx.z;
    const float* W    = d ? Wb : Wf;
    const float* bias = d ? bb : bf;
    int col0 = blockIdx.x * 64;
    int row0 = blockIdx.y * 64;
    int t  = row0 >> 8;
    int m0 = row0 & 255;
    int xt = d ? (TX - 1 - t) : t;

    int tid = threadIdx.x;
    int wid = tid >> 5;
    int lr = tid >> 1, kh = tid & 1;

    {
        const float* xrow = X + ((size_t)(m0 + lr) * TX + xt) * FDIM + kh * 64;
        #pragma unroll
        for (int j = 0; j < 16; j++) {
            float4 v = *(const float4*)(xrow + j * 4);
            float vv[4] = {v.x, v.y, v.z, v.w};
            #pragma unroll
            for (int e = 0; e < 4; e++) {
                __nv_bfloat16 hi = __float2bfloat16(vv[e]);
                __nv_bfloat16 lo = __float2bfloat16(vv[e] - __bfloat162float(hi));
                Ahi[lr * XALD + kh * 64 + j * 4 + e] = hi;
                Alo[lr * XALD + kh * 64 + j * 4 + e] = lo;
            }
        }
    }
    {
        int c = col0 + lr;
        const float* wrow = W + (size_t)c * FDIM + kh * 64;
        #pragma unroll
        for (int j = 0; j < 16; j++) {
            float4 v = *(const float4*)(wrow + j * 4);
            float vv[4] = {v.x, v.y, v.z, v.w};
            #pragma unroll
            for (int e = 0; e < 4; e++) {
                int k = kh * 64 + j * 4 + e;
                __nv_bfloat16 hi = __float2bfloat16(vv[e]);
                __nv_bfloat16 lo = __float2bfloat16(vv[e] - __bfloat162float(hi));
                Bhi[k * XBLD + lr] = hi;
                Blo[k * XBLD + lr] = lo;
            }
        }
    }
    __syncthreads();

    wmma::fragment<wmma::accumulator, 16, 16, 16, float> acc[4];
    #pragma unroll
    for (int n = 0; n < 4; n++) wmma::fill_fragment(acc[n], 0.f);
    int wm = wid * 16;
    #pragma unroll 1
    for (int pass = 0; pass < 3; pass++) {
        const __nv_bfloat16* Ap = (pass == 2) ? Alo : Ahi;
        const __nv_bfloat16* Bp = (pass == 1) ? Blo : Bhi;
        #pragma unroll 1
        for (int kf = 0; kf < 8; kf++) {
            wmma::fragment<wmma::matrix_a, 16, 16, 16, __nv_bfloat16, wmma::row_major> af;
            wmma::load_matrix_sync(af, Ap + wm * XALD + kf * 16, XALD);
            #pragma unroll
            for (int n = 0; n < 4; n++) {
                wmma::fragment<wmma::matrix_b, 16, 16, 16, __nv_bfloat16, wmma::row_major> bfr;
                wmma::load_matrix_sync(bfr, Bp + (kf * 16) * XBLD + n * 16, XBLD);
                wmma::mma_sync(acc[n], af, bfr, acc[n]);
            }
        }
    }
    #pragma unroll
    for (int n = 0; n < 4; n++)
        wmma::store_matrix_sync(Cs + wm * XCLD + n * 16, acc[n], XCLD, wmma::mem_row_major);
    __syncthreads();

    {
        int mloc = tid >> 1, half = tid & 1;
        int m = m0 + mloc;
        float* gp = &g_gin[d][t][m][0];
        int g = col0 >> 8;
        #pragma unroll
        for (int j = 0; j < 32; j++) {
            int cg = col0 + half * 32 + j;
            int u = cg & 255;
            gp[u * 4 + g] = Cs[mloc * XCLD + half * 32 + j] + __ldg(&bias[cg]);
        }
    }
}

// ---------------- m-independent persistent recurrence: NO inter-CTA sync ----------------
// grid (16 m-tiles, 2 dirs) = 32 CTAs, 256 threads. CTA owns 16 m x ALL 256 units.
// h planes live in CTA smem; W (1MB hi/lo) streamed from L2 per step in 8 K=32 chunks.
__global__ void __launch_bounds__(256, 1) lstm_all_kernel()
{
    extern __shared__ char smc[];
    __nv_bfloat16* Bhi = (__nv_bfloat16*)smc;           // [RK][LWLD]
    __nv_bfloat16* Blo = Bhi + RK * LWLD;
    __nv_bfloat16* Ahi = Blo + RK * LWLD;               // [16][LALD]
    __nv_bfloat16* Alo = Ahi + 16 * LALD;
    float*         Cs  = (float*)(Alo + 16 * LALD);     // [16][LCLD]

    int m0 = blockIdx.x * 16;
    int d  = blockIdx.y;
    int tid = threadIdx.x;
    int wid = tid >> 5;                                  // 8 warps: cols [wid*128, +128)

    // zero A planes (t=0 h state)
    {
        uint4 z4 = make_uint4(0u, 0u, 0u, 0u);
        for (int i = tid; i < 16 * (LALD / 8); i += 256) {
            ((uint4*)Ahi)[i] = z4;
            ((uint4*)Alo)[i] = z4;
        }
    }

    // epilogue thread map: m = tid>>4, units [ug*16, +16)
    int me = tid >> 4, ug = tid & 15;
    float cst[16];
    #pragma unroll
    for (int i = 0; i < 16; i++) cst[i] = 0.f;
    __syncthreads();

    for (int t = 0; t < TX; t++) {
        wmma::fragment<wmma::accumulator, 16, 16, 16, float> acc[8];
        #pragma unroll
        for (int n = 0; n < 8; n++) wmma::fill_fragment(acc[n], 0.f);

        #pragma unroll 1
        for (int kc = 0; kc < NA / RK; kc++) {
            // fill W chunk (hi+lo): 64 rows x 128 uint4
            {
                const uint4* srcH = (const uint4*)&g_whx[d][0][kc * RK][0];
                const uint4* srcL = (const uint4*)&g_whx[d][1][kc * RK][0];
                #pragma unroll
                for (int i = 0; i < 32; i++) {
                    int idx = tid + i * 256;             // 0..8191
                    int row = idx >> 7, q = idx & 127;   // row 0..63
                    int pl = row >> 5, k = row & 31;
                    uint4 v = __ldcg((pl ? srcL : srcH) + (k << 7) + q);
                    uint4* dst = (uint4*)(pl ? Blo : Bhi);
                    dst[k * (LWLD / 8) + q] = v;
                }
            }
            __syncthreads();

            #pragma unroll 1
            for (int pass = 0; pass < 3; pass++) {
                const __nv_bfloat16* Ap = (pass == 2) ? Alo : Ahi;
                const __nv_bfloat16* Bp = (pass == 1) ? Blo : Bhi;
                #pragma unroll
                for (int kf = 0; kf < 2; kf++) {
                    wmma::fragment<wmma::matrix_a, 16, 16, 16, __nv_bfloat16, wmma::row_major> af;
                    wmma::load_matrix_sync(af, Ap + (kc * RK + kf * 16), LALD);
                    #pragma unroll
                    for (int n = 0; n < 8; n++) {
                        wmma::fragment<wmma::matrix_b, 16, 16, 16, __nv_bfloat16, wmma::row_major> bfr;
                        wmma::load_matrix_sync(bfr, Bp + (kf * 16) * LWLD + wid * 128 + n * 16, LWLD);
                        wmma::mma_sync(acc[n], af, bfr, acc[n]);
                    }
                }
            }
            __syncthreads();
        }

        #pragma unroll
        for (int n = 0; n < 8; n++)
            wmma::store_matrix_sync(Cs + wid * 128 + n * 16, acc[n], LCLD, wmma::mem_row_major);
        __syncthreads();

        // ---- epilogue: thread (me, ug): 16 units, 4 gates each ----
        int tw = d ? (TX - 1 - t) : t;
        const float* gp = &g_gin[d][t][m0 + me][ug * 64];
        const float* cp = &Cs[me * LCLD + ug * 64];
        float h16[16];
        #pragma unroll
        for (int j = 0; j < 16; j++) {
            float4 gv4 = __ldg((const float4*)(gp + j * 4));
            float iv = cp[j * 4 + 0] + gv4.x;
            float fv = cp[j * 4 + 1] + gv4.y;
            float gv = cp[j * 4 + 2] + gv4.z;
            float ov = cp[j * 4 + 3] + gv4.w;
            float cn = fsig(fv) * cst[j] + fsig(iv) * ftanh(gv);
            cst[j] = cn;
            h16[j] = fsig(ov) * ftanh(cn);
        }
        __syncthreads();   // all Cs reads done before A overwrite

        // write h -> A planes (next step) + g_abf (global)
        {
            uint32_t ph[8], pl[8];
            #pragma unroll
            for (int j = 0; j < 8; j++) {
                float f0 = h16[2 * j], f1 = h16[2 * j + 1];
                __nv_bfloat162 bh = __float22bfloat162_rn(make_float2(f0, f1));
                float r0 = f0 - __bfloat162float(__low2bfloat16(bh));
                float r1 = f1 - __bfloat162float(__high2bfloat16(bh));
                __nv_bfloat162 bl = __float22bfloat162_rn(make_float2(r0, r1));
                ph[j] = *(uint32_t*)&bh;
                pl[j] = *(uint32_t*)&bl;
            }
            uint4* ah = (uint4*)&Ahi[me * LALD + ug * 16];
            uint4* al = (uint4*)&Alo[me * LALD + ug * 16];
            ah[0] = make_uint4(ph[0], ph[1], ph[2], ph[3]);
            ah[1] = make_uint4(ph[4], ph[5], ph[6], ph[7]);
            al[0] = make_uint4(pl[0], pl[1], pl[2], pl[3]);
            al[1] = make_uint4(pl[4], pl[5], pl[6], pl[7]);
            uint4* ab = (uint4*)&g_abf[tw][m0 + me][d * 128 + ug * 8];
            ab[0] = make_uint4(ph[0], ph[1], ph[2], ph[3]);
            ab[1] = make_uint4(ph[4], ph[5], ph[6], ph[7]);
        }
        __syncthreads();
    }
}

// ---------------- hoisted attention energies: Ea = a @ W1a^T (bf16 a) ----------------
__global__ void ea_kernel(const float* __restrict__ W1)
{
    __shared__ float W1t[512][AH];
    int tid = threadIdx.x;
    for (int i = tid; i < 512 * AH; i += 256) {
        int h = i / 512, k = i - h * 512;
        W1t[k][h] = W1[h * 1024 + k];
    }
    __syncthreads();
    int r = blockIdx.x * 256 + tid;
    const unsigned* arow = &g_abf[0][0][0] + (size_t)r * (NS / 2);
    float e[AH] = {};
    for (int k2 = 0; k2 < 256; k2 += 2) {
        uint2 p2 = *(const uint2*)(arow + k2);
        float2 v0 = __bfloat1622float2(*(__nv_bfloat162*)&p2.x);
        float2 v1 = __bfloat1622float2(*(__nv_bfloat162*)&p2.y);
        int k = k2 * 2;
        #pragma unroll
        for (int h = 0; h < AH; h++)
            e[h] += v0.x * W1t[k][h] + v0.y * W1t[k + 1][h]
                  + v1.x * W1t[k + 2][h] + v1.y * W1t[k + 3][h];
    }
    int tt = r >> 8;
    int m = r & 255;
    float* eo = &g_Ea[m][tt][0];
    #pragma unroll
    for (int h = 0; h < AH; h++) eo[h] = e[h];
}

// ---------------- attention (R15-validated; emits ctx bf16 planes) ----------------
__global__ void attention_kernel(const float* __restrict__ W1, const float* __restrict__ b1,
                                 const float* __restrict__ W2, const float* __restrict__ b2,
                                 int pin)
{
    int m = blockIdx.x;
    int tid = threadIdx.x;
    int lane = tid & 31, warp = tid >> 5;
    __shared__ float Ss[NS];
    __shared__ float EsSh[AH];
    __shared__ float alpha[TX];
    __shared__ float red[8];
    __shared__ float sh_mx, sh_sum;

    const float* s_in = &g_sbuf[pin][m][0];
    Ss[tid] = s_in[tid];
    Ss[tid + 256] = s_in[tid + 256];
    __syncthreads();

    for (int h = warp; h < AH; h += 8) {
        float p = 0.f;
        for (int k = lane; k < NS; k += 32)
            p += Ss[k] * W1[h * 1024 + 512 + k];
        #pragma unroll
        for (int o = 16; o; o >>= 1) p += __shfl_xor_sync(0xffffffffu, p, o);
        if (lane == 0) EsSh[h] = p + b1[h];
    }
    __syncthreads();

    float sc = b2[0];
    {
        const float* ea = &g_Ea[m][tid][0];
        #pragma unroll
        for (int h = 0; h < AH; h++)
            sc += W2[h] * tanhf(ea[h] + EsSh[h]);
    }
    sc = fmaxf(sc, 0.f);

    float v = sc;
    #pragma unroll
    for (int o = 16; o; o >>= 1) v = fmaxf(v, __shfl_xor_sync(0xffffffffu, v, o));
    if (lane == 0) red[warp] = v;
    __syncthreads();
    if (tid == 0) {
        float mx = red[0];
        #pragma unroll
        for (int i = 1; i < 8; i++) mx = fmaxf(mx, red[i]);
        sh_mx = mx;
    }
    __syncthreads();
    float ev = expf(sc - sh_mx);
    float sv = ev;
    #pragma unroll
    for (int o = 16; o; o >>= 1) sv += __shfl_xor_sync(0xffffffffu, sv, o);
    if (lane == 0) red[warp] = sv;
    __syncthreads();
    if (tid == 0) {
        float s = 0.f;
        #pragma unroll
        for (int i = 0; i < 8; i++) s += red[i];
        sh_sum = s;
    }
    __syncthreads();
    alpha[tid] = ev / sh_sum;
    __syncthreads();

    const unsigned* ab = &g_abf[0][m][0] + tid;
    float ax = 0.f, ay = 0.f;
    #pragma unroll 8
    for (int t2 = 0; t2 < TX; t2++) {
        unsigned p = ab[(size_t)t2 * MB * (NS / 2)];
        __nv_bfloat162 b2v = *(__nv_bfloat162*)&p;
        float2 vv = __bfloat1622float2(b2v);
        float al = alpha[t2];
        ax += al * vv.x;
        ay += al * vv.y;
    }
    __nv_bfloat162 bh = __float22bfloat162_rn(make_float2(ax, ay));
    float r0 = ax - __bfloat162float(__low2bfloat16(bh));
    float r1 = ay - __bfloat162float(__high2bfloat16(bh));
    __nv_bfloat162 bl = __float22bfloat162_rn(make_float2(r0, r1));
    g_cx[0][m][tid] = *(unsigned*)&bh;
    g_cx[1][m][tid] = *(unsigned*)&bl;
}

// ---------------- decoder LSTM cell (R15-validated wmma) ----------------
__global__ void __launch_bounds__(128) dec_cell_kernel(const float* __restrict__ bc, int pin)
{
    extern __shared__ char dsm[];
    __nv_bfloat16* Bhi = (__nv_bfloat16*)dsm;
    __nv_bfloat16* Blo = Bhi + 256 * BLD;
    __nv_bfloat16* Ahi = Blo + 256 * BLD;
    __nv_bfloat16* Alo = Ahi + 64 * DALD;
    float*         Cs  = (float*)(Alo + 64 * DALD);

    int u0c = blockIdx.x * 64;
    int m0  = blockIdx.y * 64;
    int tid = threadIdx.x;
    int wid = tid >> 5;

    wmma::fragment<wmma::accumulator, 16, 16, 16, float> acc[4];
    #pragma unroll
    for (int n = 0; n < 4; n++) wmma::fill_fragment(acc[n], 0.f);
    int wm = wid * 16;

    #pragma unroll 1
    for (int kc = 0; kc < 4; kc++) {
        {
            const uint4* srcH;
            const uint4* srcL;
            int koff = kc & 1;
            if (kc < 2) {
                srcH = (const uint4*)&g_cx[0][m0][0];
                srcL = (const uint4*)&g_cx[1][m0][0];
            } else {
                srcH = (const uint4*)&g_sx[pin][0][m0][0];
                srcL = (const uint4*)&g_sx[pin][1][m0][0];
            }
            for (int idx = tid; idx < 64 * 32; idx += 128) {
                int m = idx >> 5, w4 = idx & 31;
                int src_i = m * 64 + koff * 32 + w4;
                ((uint4*)Ahi)[m * (DALD / 8) + w4] = __ldcg(&srcH[src_i]);
                ((uint4*)Alo)[m * (DALD / 8) + w4] = __ldcg(&srcL[src_i]);
            }
        }
        for (int idx = tid; idx < 256 * 8; idx += 128) {
            int k = idx >> 3, q = idx & 7;
            ((uint4*)Bhi)[k * (BLD / 8) + q] =
                __ldcg((const uint4*)&g_wdx[0][kc * 256 + k][u0c] + q);
            ((uint4*)Blo)[k * (BLD / 8) + q] =
                __ldcg((const uint4*)&g_wdx[1][kc * 256 + k][u0c] + q);
        }
        __syncthreads();

        #pragma unroll 1
        for (int pass = 0; pass < 3; pass++) {
            const __nv_bfloat16* Ap = (pass == 2) ? Alo : Ahi;
            const __nv_bfloat16* Bp = (pass == 1) ? Blo : Bhi;
            #pragma unroll 1
            for (int k = 0; k < 16; k++) {
                wmma::fragment<wmma::matrix_a, 16, 16, 16, __nv_bfloat16, wmma::row_major> af;
                wmma::load_matrix_sync(af, Ap + wm * DALD + k * 16, DALD);
                #pragma unroll
                for (int n = 0; n < 4; n++) {
                    wmma::fragment<wmma::matrix_b, 16, 16, 16, __nv_bfloat16, wmma::row_major> bfr;
                    wmma::load_matrix_sync(bfr, Bp + (k * 16) * BLD + n * 16, BLD);
                    wmma::mma_sync(acc[n], af, bfr, acc[n]);
                }
            }
        }
        __syncthreads();
    }
    #pragma unroll
    for (int n = 0; n < 4; n++)
        wmma::store_matrix_sync(Cs + wm * CLD + n * 16, acc[n], CLD, wmma::mem_row_major);
    __syncthreads();

    int mloc = tid >> 1, half = tid & 1;
    int m = m0 + mloc;
    int ub = u0c / 4 + half * 8;
    float s8[8];
    #pragma unroll
    for (int j = 0; j < 8; j++) {
        int u = ub + j;
        int col = half * 32 + j * 4;
        float iv = Cs[mloc * CLD + col + 0] + __ldg(&bc[0 * NS + u]);
        float fv = Cs[mloc * CLD + col + 1] + __ldg(&bc[1 * NS + u]);
        float gv = Cs[mloc * CLD + col + 2] + __ldg(&bc[2 * NS + u]);
        float ov = Cs[mloc * CLD + col + 3] + __ldg(&bc[3 * NS + u]);
        float co = g_cdec[m][u];
        float cn = sigf(fv) * co + sigf(iv) * tanhf(gv);
        g_cdec[m][u] = cn;
        s8[j] = sigf(ov) * tanhf(cn);
    }
    {
        float* sb = &g_sbuf[1 - pin][m][ub];
        *(float4*)&sb[0] = make_float4(s8[0], s8[1], s8[2], s8[3]);
        *(float4*)&sb[4] = make_float4(s8[4], s8[5], s8[6], s8[7]);
        uint32_t phw[4], plw[4];
        #pragma unroll
        for (int j = 0; j < 4; j++) {
            float f0 = s8[2 * j], f1 = s8[2 * j + 1];
            __nv_bfloat162 bh = __float22bfloat162_rn(make_float2(f0, f1));
            float r0 = f0 - __bfloat162float(__low2bfloat16(bh));
            float r1 = f1 - __bfloat162float(__high2bfloat16(bh));
            __nv_bfloat162 bl = __float22bfloat162_rn(make_float2(r0, r1));
            phw[j] = *(uint32_t*)&bh;
            plw[j] = *(uint32_t*)&bl;
        }
        *(uint4*)&g_sx[1 - pin][0][m][ub >> 1] = make_uint4(phw[0], phw[1], phw[2], phw[3]);
        *(uint4*)&g_sx[1 - pin][1][m][ub >> 1] = make_uint4(plw[0], plw[1], plw[2], plw[3]);
    }
}

// ---------------- output projection (R15-validated wmma) ----------------
__global__ void __launch_bounds__(128) fc_kernel(const float* __restrict__ bfc,
                                                 float* __restrict__ outp, int ps, int ty)
{
    extern __shared__ char fsm[];
    __nv_bfloat16* Bhi = (__nv_bfloat16*)fsm;
    __nv_bfloat16* Blo = Bhi + 256 * BLD;
    __nv_bfloat16* Ahi = Blo + 256 * BLD;
    __nv_bfloat16* Alo = Ahi + 64 * DALD;
    float*         Cs  = (float*)(Alo + 64 * DALD);

    int col0 = blockIdx.x * 64;
    int m0   = blockIdx.y * 64;
    int tid = threadIdx.x;
    int wid = tid >> 5;

    wmma::fragment<wmma::accumulator, 16, 16, 16, float> acc[4];
    #pragma unroll
    for (int n = 0; n < 4; n++) wmma::fill_fragment(acc[n], 0.f);
    int wm = wid * 16;

    #pragma unroll 1
    for (int kc = 0; kc < 2; kc++) {
        {
            const uint4* srcH = (const uint4*)&g_sx[ps][0][m0][0];
            const uint4* srcL = (const uint4*)&g_sx[ps][1][m0][0];
            for (int idx = tid; idx < 64 * 32; idx += 128) {
                int m = idx >> 5, w4 = idx & 31;
                int src_i = m * 64 + kc * 32 + w4;
                ((uint4*)Ahi)[m * (DALD / 8) + w4] = __ldcg(&srcH[src_i]);
                ((uint4*)Alo)[m * (DALD / 8) + w4] = __ldcg(&srcL[src_i]);
            }
        }
        for (int idx = tid; idx < 256 * 8; idx += 128) {
            int k = idx >> 3, q = idx & 7;
            ((uint4*)Bhi)[k * (BLD / 8) + q] =
                __ldcg((const uint4*)&g_wfx[0][kc * 256 + k][col0] + q);
            ((uint4*)Blo)[k * (BLD / 8) + q] =
                __ldcg((const uint4*)&g_wfx[1][kc * 256 + k][col0] + q);
        }
        __syncthreads();

        #pragma unroll 1
        for (int pass = 0; pass < 3; pass++) {
            const __nv_bfloat16* Ap = (pass == 2) ? Alo : Ahi;
            const __nv_bfloat16* Bp = (pass == 1) ? Blo : Bhi;
            #pragma unroll 1
            for (int k = 0; k < 16; k++) {
                wmma::fragment<wmma::matrix_a, 16, 16, 16, __nv_bfloat16, wmma::row_major> af;
                wmma::load_matrix_sync(af, Ap + wm * DALD + k * 16, DALD);
                #pragma unroll
                for (int n = 0; n < 4; n++) {
                    wmma::fragment<wmma::matrix_b, 16, 16, 16, __nv_bfloat16, wmma::row_major> bfr;
                    wmma::load_matrix_sync(bfr, Bp + (k * 16) * BLD + n * 16, BLD);
                    wmma::mma_sync(acc[n], af, bfr, acc[n]);
                }
            }
        }
        __syncthreads();
    }
    #pragma unroll
    for (int n = 0; n < 4; n++)
        wmma::store_matrix_sync(Cs + wm * CLD + n * 16, acc[n], CLD, wmma::mem_row_major);
    __syncthreads();

    int mloc = tid >> 1, half = tid & 1;
    int m = m0 + mloc;
    float* op = &outp[((size_t)m * TYD + ty) * VOC + col0 + half * 32];
    #pragma unroll
    for (int q = 0; q < 8; q++) {
        int j = q * 4;
        float4 bv = *(const float4*)&bfc[col0 + half * 32 + j];
        *(float4*)&op[j] = make_float4(Cs[mloc * CLD + half * 32 + j + 0] + bv.x,
                                       Cs[mloc * CLD + half * 32 + j + 1] + bv.y,
                                       Cs[mloc * CLD + half * 32 + j + 2] + bv.z,
                                       Cs[mloc * CLD + half * 32 + j + 3] + bv.w);
    }
}

// ---------------- launch ----------------
extern "C" void kernel_launch(void* const* d_in, const int* in_sizes, int n_in,
                              void* d_out, int out_size)
{
    const float* X     = (const float*)d_in[0];
    const float* Wih_f = (const float*)d_in[1];
    const float* Whh_f = (const float*)d_in[2];
    const float* b_f   = (const float*)d_in[3];
    const float* Wih_b = (const float*)d_in[4];
    const float* Whh_b = (const float*)d_in[5];
    const float* b_b   = (const float*)d_in[6];
    const float* W1    = (const float*)d_in[7];
    const float* b1    = (const float*)d_in[8];
    const float* W2    = (const float*)d_in[9];
    const float* b2    = (const float*)d_in[10];
    const float* Wc_ih = (const float*)d_in[11];
    const float* Wc_hh = (const float*)d_in[12];
    const float* bc    = (const float*)d_in[13];
    const float* Wfc   = (const float*)d_in[14];
    const float* bfc   = (const float*)d_in[15];
    float* outp = (float*)d_out;

    const int XPROJ_SMEM = (2 * 128 * XBLD + 2 * 64 * XALD) * 2 + 64 * XCLD * 4;
    const int DEC_SMEM   = (2 * 256 * BLD + 2 * 64 * DALD) * 2 + 64 * CLD * 4;
    const int LSTM_SMEM  = (2 * RK * LWLD + 2 * 16 * LALD) * 2 + 16 * LCLD * 4;  // 215,040 B

    static int smem_set = 0;
    if (!smem_set) {
        cudaFuncSetAttribute(lstm_all_kernel,
                             cudaFuncAttributeMaxDynamicSharedMemorySize, LSTM_SMEM);
        cudaFuncSetAttribute(xproj_kernel,
                             cudaFuncAttributeMaxDynamicSharedMemorySize, XPROJ_SMEM);
        cudaFuncSetAttribute(dec_cell_kernel,
                             cudaFuncAttributeMaxDynamicSharedMemorySize, DEC_SMEM);
        cudaFuncSetAttribute(fc_kernel,
                             cudaFuncAttributeMaxDynamicSharedMemorySize, DEC_SMEM);
        smem_set = 1;
    }

    init_dec_kernel<<<512, 256>>>();
    whx_prep<<<2048, 256>>>(Whh_f, Whh_b);
    wdx_prep<<<8192, 256>>>(Wc_ih, Wc_hh);
    wfx_prep<<<2048, 256>>>(Wfc);
    xproj_kernel<<<dim3(16, 1024, 2), 128, XPROJ_SMEM>>>(X, Wih_f, b_f, Wih_b, b_b);
    lstm_all_kernel<<<dim3(16, 2), 256, LSTM_SMEM>>>();
    ea_kernel<<<256, 256>>>(W1);

    int pin = 0;
    for (int ty = 0; ty < TYD; ty++) {
        attention_kernel<<<MB, 256>>>(W1, b1, W2, b2, pin);
        dec_cell_kernel<<<dim3(32, 4), 128, DEC_SMEM>>>(bc, pin);
        fc_kernel<<<dim3(16, 4), 128, DEC_SMEM>>>(bfc, outp, 1 - pin, ty);
        pin = 1 - pin;
    }
}

// round 17
// speedup vs baseline: 2.1466x; 2.1466x over previous
#include <cuda_runtime.h>
#include <cuda_bf16.h>
#include <math.h>
#include <stdint.h>
#include <mma.h>

using namespace nvcuda;

#define MB   256
#define TX   256
#define FDIM 128
#define NA   256
#define NS   512
#define VOC  1024
#define AH   10
#define TYD  10

#define BLD 72     // B smem leading dim (bf16)
#define ALD 272    // lstm A smem leading dim (bf16)
#define CLD 72     // C smem leading dim (float)

#define XBLD 72
#define XALD 136
#define XCLD 72

#define DALD 264   // decoder A smem leading dim

// ---------------- scratch ----------------
__device__ float    g_gin[2][TX][MB][4 * NA];   // [m][u*4+g]
__device__ unsigned g_abf[TX][MB][NS / 2];      // bf16x2 encoder states
__device__ unsigned g_hx[2][2][2][MB][NA / 2];  // [dir][buf][hi/lo][m][k2]
__device__ float    g_Ea[MB][TX][AH];
__device__ unsigned g_cx[2][MB][NS / 2];        // ctx bf16 planes
__device__ unsigned g_sx[2][2][MB][NS / 2];     // s planes [buf][pl][m][k2]
__device__ float    g_sbuf[2][MB][NS];
__device__ float    g_cdec[MB][NS];
__device__ __nv_bfloat16 g_wdx[2][1024][2048];  // dec W planes [pl][k][c=u*4+g]
__device__ __nv_bfloat16 g_wfx[2][512][1024];   // fc  W planes
__device__ unsigned g_bar[8][32];

__device__ __forceinline__ float sigf(float x) { return 1.f / (1.f + expf(-x)); }
__device__ __forceinline__ float fsig(float x) { return __fdividef(1.f, 1.f + __expf(-x)); }
__device__ __forceinline__ float ftanh(float x) { return 1.f - __fdividef(2.f, __expf(2.f * x) + 1.f); }

__global__ void zero_bar_kernel()
{
    int i = threadIdx.x;
    if (i < 256) ((unsigned*)g_bar)[i] = 0u;
}

__global__ void init_dec_kernel()
{
    int i = blockIdx.x * 256 + threadIdx.x;
    if (i < MB * NS) {
        (&g_sbuf[0][0][0])[i] = 0.f;
        (&g_cdec[0][0])[i] = 0.f;
        ((unsigned*)&g_sx[0][0][0][0])[i] = 0u;
    }
}

// ---------------- weight-split preps ----------------
__global__ void wdx_prep(const float* __restrict__ Wc_ih, const float* __restrict__ Wc_hh)
{
    int idx = blockIdx.x * 256 + threadIdx.x;
    int k = idx >> 11, c = idx & 2047;
    int u = c >> 2, g = c & 3;
    float w = (k < NS) ? Wc_ih[(size_t)(g * NS + u) * NS + k]
                       : Wc_hh[(size_t)(g * NS + u) * NS + (k - NS)];
    __nv_bfloat16 hi = __float2bfloat16(w);
    __nv_bfloat16 lo = __float2bfloat16(w - __bfloat162float(hi));
    g_wdx[0][k][c] = hi;
    g_wdx[1][k][c] = lo;
}

__global__ void wfx_prep(const float* __restrict__ Wfc)
{
    int idx = blockIdx.x * 256 + threadIdx.x;
    int k = idx >> 10, c = idx & 1023;
    float w = Wfc[(size_t)c * NS + k];
    __nv_bfloat16 hi = __float2bfloat16(w);
    __nv_bfloat16 lo = __float2bfloat16(w - __bfloat162float(hi));
    g_wfx[0][k][c] = hi;
    g_wfx[1][k][c] = lo;
}

// ---------------- encoder input projection (R14-validated wmma) ----------------
__global__ void __launch_bounds__(128) xproj_kernel(const float* __restrict__ X,
                             const float* __restrict__ Wf, const float* __restrict__ bf,
                             const float* __restrict__ Wb, const float* __restrict__ bb)
{
    extern __shared__ char xsm[];
    __nv_bfloat16* Bhi = (__nv_bfloat16*)xsm;
    __nv_bfloat16* Blo = Bhi + 128 * XBLD;
    __nv_bfloat16* Ahi = Blo + 128 * XBLD;
    __nv_bfloat16* Alo = Ahi + 64 * XALD;
    float*         Cs  = (float*)(Alo + 64 * XALD);

    int d = blockIdx.z;
    const float* W    = d ? Wb : Wf;
    const float* bias = d ? bb : bf;
    int col0 = blockIdx.x * 64;
    int row0 = blockIdx.y * 64;
    int t  = row0 >> 8;
    int m0 = row0 & 255;
    int xt = d ? (TX - 1 - t) : t;

    int tid = threadIdx.x;
    int wid = tid >> 5;
    int lr = tid >> 1, kh = tid & 1;

    {
        const float* xrow = X + ((size_t)(m0 + lr) * TX + xt) * FDIM + kh * 64;
        #pragma unroll
        for (int j = 0; j < 16; j++) {
            float4 v = *(const float4*)(xrow + j * 4);
            float vv[4] = {v.x, v.y, v.z, v.w};
            #pragma unroll
            for (int e = 0; e < 4; e++) {
                __nv_bfloat16 hi = __float2bfloat16(vv[e]);
                __nv_bfloat16 lo = __float2bfloat16(vv[e] - __bfloat162float(hi));
                Ahi[lr * XALD + kh * 64 + j * 4 + e] = hi;
                Alo[lr * XALD + kh * 64 + j * 4 + e] = lo;
            }
        }
    }
    {
        int c = col0 + lr;
        const float* wrow = W + (size_t)c * FDIM + kh * 64;
        #pragma unroll
        for (int j = 0; j < 16; j++) {
            float4 v = *(const float4*)(wrow + j * 4);
            float vv[4] = {v.x, v.y, v.z, v.w};
            #pragma unroll
            for (int e = 0; e < 4; e++) {
                int k = kh * 64 + j * 4 + e;
                __nv_bfloat16 hi = __float2bfloat16(vv[e]);
                __nv_bfloat16 lo = __float2bfloat16(vv[e] - __bfloat162float(hi));
                Bhi[k * XBLD + lr] = hi;
                Blo[k * XBLD + lr] = lo;
            }
        }
    }
    __syncthreads();

    wmma::fragment<wmma::accumulator, 16, 16, 16, float> acc[4];
    #pragma unroll
    for (int n = 0; n < 4; n++) wmma::fill_fragment(acc[n], 0.f);
    int wm = wid * 16;
    #pragma unroll 1
    for (int pass = 0; pass < 3; pass++) {
        const __nv_bfloat16* Ap = (pass == 2) ? Alo : Ahi;
        const __nv_bfloat16* Bp = (pass == 1) ? Blo : Bhi;
        #pragma unroll 1
        for (int kf = 0; kf < 8; kf++) {
            wmma::fragment<wmma::matrix_a, 16, 16, 16, __nv_bfloat16, wmma::row_major> af;
            wmma::load_matrix_sync(af, Ap + wm * XALD + kf * 16, XALD);
            #pragma unroll
            for (int n = 0; n < 4; n++) {
                wmma::fragment<wmma::matrix_b, 16, 16, 16, __nv_bfloat16, wmma::row_major> bfr;
                wmma::load_matrix_sync(bfr, Bp + (kf * 16) * XBLD + n * 16, XBLD);
                wmma::mma_sync(acc[n], af, bfr, acc[n]);
            }
        }
    }
    #pragma unroll
    for (int n = 0; n < 4; n++)
        wmma::store_matrix_sync(Cs + wm * XCLD + n * 16, acc[n], XCLD, wmma::mem_row_major);
    __syncthreads();

    {
        int mloc = tid >> 1, half = tid & 1;
        int m = m0 + mloc;
        float* gp = &g_gin[d][t][m][0];
        int g = col0 >> 8;
        #pragma unroll
        for (int j = 0; j < 32; j++) {
            int cg = col0 + half * 32 + j;
            int u = cg & 255;
            gp[u * 4 + g] = Cs[mloc * XCLD + half * 32 + j] + __ldg(&bias[cg]);
        }
    }
}

// ---------------- persistent recurrence (R15-validated; g_a writes removed) ----------------
__global__ void __launch_bounds__(128, 1) lstm_all_kernel(const float* __restrict__ Whf,
                                                          const float* __restrict__ Whb)
{
    extern __shared__ char smc[];
    __nv_bfloat16* Bhi = (__nv_bfloat16*)smc;
    __nv_bfloat16* Blo = Bhi + 256 * BLD;
    __nv_bfloat16* Ahi = Blo + 256 * BLD;
    __nv_bfloat16* Alo = Ahi + 64 * ALD;
    float*         Cs  = (float*)(Alo + 64 * ALD);

    int d = blockIdx.z;
    const float* W = d ? Whb : Whf;
    int u0 = blockIdx.x * 16;
    int m0 = blockIdx.y * 64;
    int tid = threadIdx.x;
    int wid = tid >> 5;
    unsigned* barp = &g_bar[d * 4 + blockIdx.y][0];

    for (int idx = tid; idx < 256 * 64; idx += 128) {
        int k = idx >> 6, c = idx & 63;
        int ul = c >> 2, g = c & 3;
        float w = W[(size_t)(g * NA + u0 + ul) * NA + k];
        __nv_bfloat16 hi = __float2bfloat16(w);
        __nv_bfloat16 lo = __float2bfloat16(w - __bfloat162float(hi));
        Bhi[k * BLD + c] = hi;
        Blo[k * BLD + c] = lo;
    }

    int mloc = tid >> 1, half = tid & 1;
    int mabs = m0 + mloc;
    float cst[8];
    #pragma unroll
    for (int i = 0; i < 8; i++) cst[i] = 0.f;

    for (int t = 0; t < TX; t++) {
        if (t > 0) {
            if (tid == 0) {
                unsigned tgt = 16u * (unsigned)t;
                unsigned v;
                do {
                    asm volatile("ld.acquire.gpu.global.u32 %0, [%1];"
                                 : "=r"(v) : "l"(barp) : "memory");
                } while (v < tgt);
            }
            __syncthreads();

            int buf = (t - 1) & 1;
            uint4* ah4 = (uint4*)Ahi;
            uint4* al4 = (uint4*)Alo;
            const uint4* ph = (const uint4*)&g_hx[d][buf][0][m0][0];
            const uint4* pl = (const uint4*)&g_hx[d][buf][1][m0][0];
            for (int idx = tid; idx < 64 * 32; idx += 128) {
                int m = idx >> 5, w4 = idx & 31;
                ah4[m * (ALD / 8) + w4] = __ldcg(&ph[idx]);
                al4[m * (ALD / 8) + w4] = __ldcg(&pl[idx]);
            }
        } else {
            uint4 z4 = make_uint4(0u, 0u, 0u, 0u);
            for (int idx = tid; idx < 64 * (ALD / 8); idx += 128) {
                ((uint4*)Ahi)[idx] = z4;
                ((uint4*)Alo)[idx] = z4;
            }
        }
        __syncthreads();

        wmma::fragment<wmma::accumulator, 16, 16, 16, float> acc[4];
        #pragma unroll
        for (int n = 0; n < 4; n++) wmma::fill_fragment(acc[n], 0.f);
        int wm = wid * 16;
        #pragma unroll 1
        for (int pass = 0; pass < 3; pass++) {
            const __nv_bfloat16* Ap = (pass == 2) ? Alo : Ahi;
            const __nv_bfloat16* Bp = (pass == 1) ? Blo : Bhi;
            #pragma unroll 1
            for (int k = 0; k < 16; k++) {
                wmma::fragment<wmma::matrix_a, 16, 16, 16, __nv_bfloat16, wmma::row_major> af;
                wmma::load_matrix_sync(af, Ap + wm * ALD + k * 16, ALD);
                #pragma unroll
                for (int n = 0; n < 4; n++) {
                    wmma::fragment<wmma::matrix_b, 16, 16, 16, __nv_bfloat16, wmma::row_major> bfr;
                    wmma::load_matrix_sync(bfr, Bp + (k * 16) * BLD + n * 16, BLD);
                    wmma::mma_sync(acc[n], af, bfr, acc[n]);
                }
            }
        }
        #pragma unroll
        for (int n = 0; n < 4; n++)
            wmma::store_matrix_sync(Cs + wm * CLD + n * 16, acc[n], CLD, wmma::mem_row_major);
        __syncthreads();

        int tw = d ? (TX - 1 - t) : t;
        int buf = t & 1;
        float gc[32];
        {
            const float4* gp = (const float4*)&g_gin[d][t][mabs][(u0 + half * 8) * 4];
            #pragma unroll
            for (int q = 0; q < 8; q++) *(float4*)&gc[q * 4] = gp[q];
        }
        float h8[8];
        #pragma unroll
        for (int j = 0; j < 8; j++) {
            int col = half * 32 + j * 4;
            float iv = Cs[mloc * CLD + col + 0] + gc[4 * j + 0];
            float fv = Cs[mloc * CLD + col + 1] + gc[4 * j + 1];
            float gv = Cs[mloc * CLD + col + 2] + gc[4 * j + 2];
            float ov = Cs[mloc * CLD + col + 3] + gc[4 * j + 3];
            float cn = fsig(fv) * cst[j] + fsig(iv) * ftanh(gv);
            cst[j] = cn;
            h8[j] = fsig(ov) * ftanh(cn);
        }
        {
            uint32_t phw[4], plw[4];
            #pragma unroll
            for (int j = 0; j < 4; j++) {
                float f0 = h8[2 * j], f1 = h8[2 * j + 1];
                __nv_bfloat162 bh = __float22bfloat162_rn(make_float2(f0, f1));
                float r0 = f0 - __bfloat162float(__low2bfloat16(bh));
                float r1 = f1 - __bfloat162float(__high2bfloat16(bh));
                __nv_bfloat162 bl = __float22bfloat162_rn(make_float2(r0, r1));
                phw[j] = *(uint32_t*)&bh;
                plw[j] = *(uint32_t*)&bl;
            }
            int woff = (u0 + half * 8) >> 1;
            uint4 vh = make_uint4(phw[0], phw[1], phw[2], phw[3]);
            uint4 vl = make_uint4(plw[0], plw[1], plw[2], plw[3]);
            __stcg((uint4*)&g_hx[d][buf][0][mabs][woff], vh);
            __stcg((uint4*)&g_hx[d][buf][1][mabs][woff], vl);
            *(uint4*)&g_abf[tw][mabs][(d * NA + u0) / 2 + half * 4] = vh;
        }

        __threadfence();
        __syncthreads();
        if (tid == 0)
            asm volatile("red.release.gpu.global.add.u32 [%0], %1;"
                         :: "l"(barp), "r"(1u) : "memory");
    }
}

// ---------------- hoisted attention energies (bf16 a, validated R16) ----------------
__global__ void ea_kernel(const float* __restrict__ W1)
{
    __shared__ float W1t[512][AH];
    int tid = threadIdx.x;
    for (int i = tid; i < 512 * AH; i += 256) {
        int h = i / 512, k = i - h * 512;
        W1t[k][h] = W1[h * 1024 + k];
    }
    __syncthreads();
    int r = blockIdx.x * 256 + tid;
    const unsigned* arow = &g_abf[0][0][0] + (size_t)r * (NS / 2);
    float e[AH] = {};
    for (int k2 = 0; k2 < 256; k2 += 2) {
        uint2 p2 = *(const uint2*)(arow + k2);
        float2 v0 = __bfloat1622float2(*(__nv_bfloat162*)&p2.x);
        float2 v1 = __bfloat1622float2(*(__nv_bfloat162*)&p2.y);
        int k = k2 * 2;
        #pragma unroll
        for (int h = 0; h < AH; h++)
            e[h] += v0.x * W1t[k][h] + v0.y * W1t[k + 1][h]
                  + v1.x * W1t[k + 2][h] + v1.y * W1t[k + 3][h];
    }
    int tt = r >> 8;
    int m = r & 255;
    float* eo = &g_Ea[m][tt][0];
    #pragma unroll
    for (int h = 0; h < AH; h++) eo[h] = e[h];
}

// ---------------- attention (R15-validated; emits ctx bf16 planes) ----------------
__global__ void attention_kernel(const float* __restrict__ W1, const float* __restrict__ b1,
                                 const float* __restrict__ W2, const float* __restrict__ b2,
                                 int pin)
{
    int m = blockIdx.x;
    int tid = threadIdx.x;
    int lane = tid & 31, warp = tid >> 5;
    __shared__ float Ss[NS];
    __shared__ float EsSh[AH];
    __shared__ float alpha[TX];
    __shared__ float red[8];
    __shared__ float sh_mx, sh_sum;

    const float* s_in = &g_sbuf[pin][m][0];
    Ss[tid] = s_in[tid];
    Ss[tid + 256] = s_in[tid + 256];
    __syncthreads();

    for (int h = warp; h < AH; h += 8) {
        float p = 0.f;
        for (int k = lane; k < NS; k += 32)
            p += Ss[k] * W1[h * 1024 + 512 + k];
        #pragma unroll
        for (int o = 16; o; o >>= 1) p += __shfl_xor_sync(0xffffffffu, p, o);
        if (lane == 0) EsSh[h] = p + b1[h];
    }
    __syncthreads();

    float sc = b2[0];
    {
        const float* ea = &g_Ea[m][tid][0];
        #pragma unroll
        for (int h = 0; h < AH; h++)
            sc += W2[h] * tanhf(ea[h] + EsSh[h]);
    }
    sc = fmaxf(sc, 0.f);

    float v = sc;
    #pragma unroll
    for (int o = 16; o; o >>= 1) v = fmaxf(v, __shfl_xor_sync(0xffffffffu, v, o));
    if (lane == 0) red[warp] = v;
    __syncthreads();
    if (tid == 0) {
        float mx = red[0];
        #pragma unroll
        for (int i = 1; i < 8; i++) mx = fmaxf(mx, red[i]);
        sh_mx = mx;
    }
    __syncthreads();
    float ev = expf(sc - sh_mx);
    float sv = ev;
    #pragma unroll
    for (int o = 16; o; o >>= 1) sv += __shfl_xor_sync(0xffffffffu, sv, o);
    if (lane == 0) red[warp] = sv;
    __syncthreads();
    if (tid == 0) {
        float s = 0.f;
        #pragma unroll
        for (int i = 0; i < 8; i++) s += red[i];
        sh_sum = s;
    }
    __syncthreads();
    alpha[tid] = ev / sh_sum;
    __syncthreads();

    const unsigned* ab = &g_abf[0][m][0] + tid;
    float ax = 0.f, ay = 0.f;
    #pragma unroll 8
    for (int t2 = 0; t2 < TX; t2++) {
        unsigned p = ab[(size_t)t2 * MB * (NS / 2)];
        __nv_bfloat162 b2v = *(__nv_bfloat162*)&p;
        float2 vv = __bfloat1622float2(b2v);
        float al = alpha[t2];
        ax += al * vv.x;
        ay += al * vv.y;
    }
    __nv_bfloat162 bh = __float22bfloat162_rn(make_float2(ax, ay));
    float r0 = ax - __bfloat162float(__low2bfloat16(bh));
    float r1 = ay - __bfloat162float(__high2bfloat16(bh));
    __nv_bfloat162 bl = __float22bfloat162_rn(make_float2(r0, r1));
    g_cx[0][m][tid] = *(unsigned*)&bh;
    g_cx[1][m][tid] = *(unsigned*)&bl;
}

// ---------------- decoder LSTM cell (R15-validated wmma) ----------------
__global__ void __launch_bounds__(128) dec_cell_kernel(const float* __restrict__ bc, int pin)
{
    extern __shared__ char dsm[];
    __nv_bfloat16* Bhi = (__nv_bfloat16*)dsm;
    __nv_bfloat16* Blo = Bhi + 256 * BLD;
    __nv_bfloat16* Ahi = Blo + 256 * BLD;
    __nv_bfloat16* Alo = Ahi + 64 * DALD;
    float*         Cs  = (float*)(Alo + 64 * DALD);

    int u0c = blockIdx.x * 64;
    int m0  = blockIdx.y * 64;
    int tid = threadIdx.x;
    int wid = tid >> 5;

    wmma::fragment<wmma::accumulator, 16, 16, 16, float> acc[4];
    #pragma unroll
    for (int n = 0; n < 4; n++) wmma::fill_fragment(acc[n], 0.f);
    int wm = wid * 16;

    #pragma unroll 1
    for (int kc = 0; kc < 4; kc++) {
        {
            const uint4* srcH;
            const uint4* srcL;
            int koff = kc & 1;
            if (kc < 2) {
                srcH = (const uint4*)&g_cx[0][m0][0];
                srcL = (const uint4*)&g_cx[1][m0][0];
            } else {
                srcH = (const uint4*)&g_sx[pin][0][m0][0];
                srcL = (const uint4*)&g_sx[pin][1][m0][0];
            }
            for (int idx = tid; idx < 64 * 32; idx += 128) {
                int m = idx >> 5, w4 = idx & 31;
                int src_i = m * 64 + koff * 32 + w4;
                ((uint4*)Ahi)[m * (DALD / 8) + w4] = __ldcg(&srcH[src_i]);
                ((uint4*)Alo)[m * (DALD / 8) + w4] = __ldcg(&srcL[src_i]);
            }
        }
        for (int idx = tid; idx < 256 * 8; idx += 128) {
            int k = idx >> 3, q = idx & 7;
            ((uint4*)Bhi)[k * (BLD / 8) + q] =
                __ldcg((const uint4*)&g_wdx[0][kc * 256 + k][u0c] + q);
            ((uint4*)Blo)[k * (BLD / 8) + q] =
                __ldcg((const uint4*)&g_wdx[1][kc * 256 + k][u0c] + q);
        }
        __syncthreads();

        #pragma unroll 1
        for (int pass = 0; pass < 3; pass++) {
            const __nv_bfloat16* Ap = (pass == 2) ? Alo : Ahi;
            const __nv_bfloat16* Bp = (pass == 1) ? Blo : Bhi;
            #pragma unroll 1
            for (int k = 0; k < 16; k++) {
                wmma::fragment<wmma::matrix_a, 16, 16, 16, __nv_bfloat16, wmma::row_major> af;
                wmma::load_matrix_sync(af, Ap + wm * DALD + k * 16, DALD);
                #pragma unroll
                for (int n = 0; n < 4; n++) {
                    wmma::fragment<wmma::matrix_b, 16, 16, 16, __nv_bfloat16, wmma::row_major> bfr;
                    wmma::load_matrix_sync(bfr, Bp + (k * 16) * BLD + n * 16, BLD);
                    wmma::mma_sync(acc[n], af, bfr, acc[n]);
                }
            }
        }
        __syncthreads();
    }
    #pragma unroll
    for (int n = 0; n < 4; n++)
        wmma::store_matrix_sync(Cs + wm * CLD + n * 16, acc[n], CLD, wmma::mem_row_major);
    __syncthreads();

    int mloc = tid >> 1, half = tid & 1;
    int m = m0 + mloc;
    int ub = u0c / 4 + half * 8;
    float s8[8];
    #pragma unroll
    for (int j = 0; j < 8; j++) {
        int u = ub + j;
        int col = half * 32 + j * 4;
        float iv = Cs[mloc * CLD + col + 0] + __ldg(&bc[0 * NS + u]);
        float fv = Cs[mloc * CLD + col + 1] + __ldg(&bc[1 * NS + u]);
        float gv = Cs[mloc * CLD + col + 2] + __ldg(&bc[2 * NS + u]);
        float ov = Cs[mloc * CLD + col + 3] + __ldg(&bc[3 * NS + u]);
        float co = g_cdec[m][u];
        float cn = sigf(fv) * co + sigf(iv) * tanhf(gv);
        g_cdec[m][u] = cn;
        s8[j] = sigf(ov) * tanhf(cn);
    }
    {
        float* sb = &g_sbuf[1 - pin][m][ub];
        *(float4*)&sb[0] = make_float4(s8[0], s8[1], s8[2], s8[3]);
        *(float4*)&sb[4] = make_float4(s8[4], s8[5], s8[6], s8[7]);
        uint32_t phw[4], plw[4];
        #pragma unroll
        for (int j = 0; j < 4; j++) {
            float f0 = s8[2 * j], f1 = s8[2 * j + 1];
            __nv_bfloat162 bh = __float22bfloat162_rn(make_float2(f0, f1));
            float r0 = f0 - __bfloat162float(__low2bfloat16(bh));
            float r1 = f1 - __bfloat162float(__high2bfloat16(bh));
            __nv_bfloat162 bl = __float22bfloat162_rn(make_float2(r0, r1));
            phw[j] = *(uint32_t*)&bh;
            plw[j] = *(uint32_t*)&bl;
        }
        *(uint4*)&g_sx[1 - pin][0][m][ub >> 1] = make_uint4(phw[0], phw[1], phw[2], phw[3]);
        *(uint4*)&g_sx[1 - pin][1][m][ub >> 1] = make_uint4(plw[0], plw[1], plw[2], plw[3]);
    }
}

// ---------------- output projection (R15-validated wmma) ----------------
__global__ void __launch_bounds__(128) fc_kernel(const float* __restrict__ bfc,
                                                 float* __restrict__ outp, int ps, int ty)
{
    extern __shared__ char fsm[];
    __nv_bfloat16* Bhi = (__nv_bfloat16*)fsm;
    __nv_bfloat16* Blo = Bhi + 256 * BLD;
    __nv_bfloat16* Ahi = Blo + 256 * BLD;
    __nv_bfloat16* Alo = Ahi + 64 * DALD;
    float*         Cs  = (float*)(Alo + 64 * DALD);

    int col0 = blockIdx.x * 64;
    int m0   = blockIdx.y * 64;
    int tid = threadIdx.x;
    int wid = tid >> 5;

    wmma::fragment<wmma::accumulator, 16, 16, 16, float> acc[4];
    #pragma unroll
    for (int n = 0; n < 4; n++) wmma::fill_fragment(acc[n], 0.f);
    int wm = wid * 16;

    #pragma unroll 1
    for (int kc = 0; kc < 2; kc++) {
        {
            const uint4* srcH = (const uint4*)&g_sx[ps][0][m0][0];
            const uint4* srcL = (const uint4*)&g_sx[ps][1][m0][0];
            for (int idx = tid; idx < 64 * 32; idx += 128) {
                int m = idx >> 5, w4 = idx & 31;
                int src_i = m * 64 + kc * 32 + w4;
                ((uint4*)Ahi)[m * (DALD / 8) + w4] = __ldcg(&srcH[src_i]);
                ((uint4*)Alo)[m * (DALD / 8) + w4] = __ldcg(&srcL[src_i]);
            }
        }
        for (int idx = tid; idx < 256 * 8; idx += 128) {
            int k = idx >> 3, q = idx & 7;
            ((uint4*)Bhi)[k * (BLD / 8) + q] =
                __ldcg((const uint4*)&g_wfx[0][kc * 256 + k][col0] + q);
            ((uint4*)Blo)[k * (BLD / 8) + q] =
                __ldcg((const uint4*)&g_wfx[1][kc * 256 + k][col0] + q);
        }
        __syncthreads();

        #pragma unroll 1
        for (int pass = 0; pass < 3; pass++) {
            const __nv_bfloat16* Ap = (pass == 2) ? Alo : Ahi;
            const __nv_bfloat16* Bp = (pass == 1) ? Blo : Bhi;
            #pragma unroll 1
            for (int k = 0; k < 16; k++) {
                wmma::fragment<wmma::matrix_a, 16, 16, 16, __nv_bfloat16, wmma::row_major> af;
                wmma::load_matrix_sync(af, Ap + wm * DALD + k * 16, DALD);
                #pragma unroll
                for (int n = 0; n < 4; n++) {
                    wmma::fragment<wmma::matrix_b, 16, 16, 16, __nv_bfloat16, wmma::row_major> bfr;
                    wmma::load_matrix_sync(bfr, Bp + (k * 16) * BLD + n * 16, BLD);
                    wmma::mma_sync(acc[n], af, bfr, acc[n]);
                }
            }
        }
        __syncthreads();
    }
    #pragma unroll
    for (int n = 0; n < 4; n++)
        wmma::store_matrix_sync(Cs + wm * CLD + n * 16, acc[n], CLD, wmma::mem_row_major);
    __syncthreads();

    int mloc = tid >> 1, half = tid & 1;
    int m = m0 + mloc;
    float* op = &outp[((size_t)m * TYD + ty) * VOC + col0 + half * 32];
    #pragma unroll
    for (int q = 0; q < 8; q++) {
        int j = q * 4;
        float4 bv = *(const float4*)&bfc[col0 + half * 32 + j];
        *(float4*)&op[j] = make_float4(Cs[mloc * CLD + half * 32 + j + 0] + bv.x,
                                       Cs[mloc * CLD + half * 32 + j + 1] + bv.y,
                                       Cs[mloc * CLD + half * 32 + j + 2] + bv.z,
                                       Cs[mloc * CLD + half * 32 + j + 3] + bv.w);
    }
}

// ---------------- launch ----------------
extern "C" void kernel_launch(void* const* d_in, const int* in_sizes, int n_in,
                              void* d_out, int out_size)
{
    const float* X     = (const float*)d_in[0];
    const float* Wih_f = (const float*)d_in[1];
    const float* Whh_f = (const float*)d_in[2];
    const float* b_f   = (const float*)d_in[3];
    const float* Wih_b = (const float*)d_in[4];
    const float* Whh_b = (const float*)d_in[5];
    const float* b_b   = (const float*)d_in[6];
    const float* W1    = (const float*)d_in[7];
    const float* b1    = (const float*)d_in[8];
    const float* W2    = (const float*)d_in[9];
    const float* b2    = (const float*)d_in[10];
    const float* Wc_ih = (const float*)d_in[11];
    const float* Wc_hh = (const float*)d_in[12];
    const float* bc    = (const float*)d_in[13];
    const float* Wfc   = (const float*)d_in[14];
    const float* bfc   = (const float*)d_in[15];
    float* outp = (float*)d_out;

    const int LSTM_SMEM  = (2 * 256 * BLD + 2 * 64 * ALD) * 2 + 64 * CLD * 4;
    const int XPROJ_SMEM = (2 * 128 * XBLD + 2 * 64 * XALD) * 2 + 64 * XCLD * 4;
    const int DEC_SMEM   = (2 * 256 * BLD + 2 * 64 * DALD) * 2 + 64 * CLD * 4;

    static int smem_set = 0;
    if (!smem_set) {
        cudaFuncSetAttribute(lstm_all_kernel,
                             cudaFuncAttributeMaxDynamicSharedMemorySize, LSTM_SMEM);
        cudaFuncSetAttribute(xproj_kernel,
                             cudaFuncAttributeMaxDynamicSharedMemorySize, XPROJ_SMEM);
        cudaFuncSetAttribute(dec_cell_kernel,
                             cudaFuncAttributeMaxDynamicSharedMemorySize, DEC_SMEM);
        cudaFuncSetAttribute(fc_kernel,
                             cudaFuncAttributeMaxDynamicSharedMemorySize, DEC_SMEM);
        smem_set = 1;
    }

    zero_bar_kernel<<<1, 256>>>();
    init_dec_kernel<<<512, 256>>>();
    wdx_prep<<<8192, 256>>>(Wc_ih, Wc_hh);
    wfx_prep<<<2048, 256>>>(Wfc);
    xproj_kernel<<<dim3(16, 1024, 2), 128, XPROJ_SMEM>>>(X, Wih_f, b_f, Wih_b, b_b);
    lstm_all_kernel<<<dim3(16, 4, 2), 128, LSTM_SMEM>>>(Whh_f, Whh_b);
    ea_kernel<<<256, 256>>>(W1);

    int pin = 0;
    for (int ty = 0; ty < TYD; ty++) {
        attention_kernel<<<MB, 256>>>(W1, b1, W2, b2, pin);
        dec_cell_kernel<<<dim3(32, 4), 128, DEC_SMEM>>>(bc, pin);
        fc_kernel<<<dim3(16, 4), 128, DEC_SMEM>>>(bfc, outp, 1 - pin, ty);
        pin = 1 - pin;
    }
}